// round 1
// baseline (speedup 1.0000x reference)
#include <cuda_runtime.h>
#include <cstdint>

// ---------------------------------------------------------------------------
// SelfAttention: B=4, T=2048, D=1024 (single head, width-1024), causal.
//   Q = X Wq^T / sqrt(D);  K = X Wk^T;  V = X Wv^T
//   S = Q K^T (causal);  P = softmax(S);  out = P V
// All GEMMs: TF32 tensor cores (mma.sync.m16n8k8), fp32 accumulate.
// Inputs rounded to tf32 with cvt.rna (explicitly) to avoid HMMA truncation bias.
// ---------------------------------------------------------------------------

namespace {
constexpr int BATCH = 4;
constexpr int T     = 2048;
constexpr int D     = 1024;
constexpr int MQKV  = BATCH * T;   // 8192

constexpr int BM = 128, BN = 128, BK = 32;
constexpr int SA   = BK + 4;       // padded row stride (floats) for [rows][BK] tiles
constexpr int SBNN = BN + 8;       // padded row stride for NN B tile [BK][BN]
constexpr int NT = 256;            // threads per CTA (8 warps)

constexpr int SMEM_TN = 2 * (BM * SA + BN * SA) * 4;    // 73728 B
constexpr int SMEM_NN = 2 * (BM * SA + BK * SBNN) * 4;  // 71680 B
}

// Scratch (device globals: allocation-free per harness rules)
__device__ float g_Q[(size_t)MQKV * D];
__device__ float g_K[(size_t)MQKV * D];
__device__ float g_V[(size_t)MQKV * D];
__device__ float g_S[(size_t)BATCH * T * T];

// ---------------------------------------------------------------------------
// helpers
// ---------------------------------------------------------------------------
__device__ __forceinline__ unsigned f2tf(float x) {
    unsigned r;
    asm("cvt.rna.tf32.f32 %0, %1;" : "=r"(r) : "f"(x));
    return r;
}

template <bool CVT>
__device__ __forceinline__ unsigned ldcvt(float v) {
    return CVT ? f2tf(v) : __float_as_uint(v);
}

__device__ __forceinline__ void mma8(float* c, const unsigned* a, const unsigned* b) {
    asm volatile(
        "mma.sync.aligned.m16n8k8.row.col.f32.tf32.tf32.f32 "
        "{%0,%1,%2,%3}, {%4,%5,%6,%7}, {%8,%9}, {%0,%1,%2,%3};"
        : "+f"(c[0]), "+f"(c[1]), "+f"(c[2]), "+f"(c[3])
        : "r"(a[0]), "r"(a[1]), "r"(a[2]), "r"(a[3]), "r"(b[0]), "r"(b[1]));
}

__device__ __forceinline__ void cp16(void* s, const void* g) {
    unsigned sa = (unsigned)__cvta_generic_to_shared(s);
    asm volatile("cp.async.cg.shared.global [%0], [%1], 16;" ::"r"(sa), "l"(g));
}
__device__ __forceinline__ void cp_commit() { asm volatile("cp.async.commit_group;"); }
__device__ __forceinline__ void cp_wait1()  { asm volatile("cp.async.wait_group 1;"); }

// ---------------------------------------------------------------------------
// GEMM TN:  C[m,n] = alpha * sum_k A[m,k] * B[n,k]
//   A: [M,K] row-major (lda), B: [N,K] row-major (ldb), C row-major (ldc)
//   grid: (N/BN, M/BM, batch); CAUSAL skips tiles with bx > by.
//   ROUND: round outputs to tf32 (for downstream MMA exactness).
// ---------------------------------------------------------------------------
template <bool CVT, bool CAUSAL, bool ROUND>
__global__ void __launch_bounds__(NT)
gemm_tn_kernel(const float* __restrict__ A, const float* __restrict__ B,
               float* __restrict__ C, int K, int lda, int ldb, int ldc,
               long long sA, long long sB, long long sC, float alpha) {
    const int bx = blockIdx.x, by = blockIdx.y, bz = blockIdx.z;
    if (CAUSAL && bx > by) return;

    extern __shared__ float smem[];
    float* As = smem;                 // [2][BM][SA]
    float* Bs = smem + 2 * BM * SA;   // [2][BN][SA]

    const float* Ab = A + (size_t)bz * sA + (size_t)by * BM * lda;
    const float* Bb = B + (size_t)bz * sB + (size_t)bx * BN * ldb;

    const int tid = threadIdx.x, lane = tid & 31, wid = tid >> 5;
    const int wm = wid >> 2, wn = wid & 3;   // 2 x 4 warp grid, 64x32 per warp

    float acc[4][4][4];
#pragma unroll
    for (int i = 0; i < 4; i++)
#pragma unroll
        for (int j = 0; j < 4; j++)
#pragma unroll
            for (int k = 0; k < 4; k++) acc[i][j][k] = 0.f;

    auto load_stage = [&](int buf, int kt) {
        {
            float* s = As + buf * BM * SA;
            const float* g = Ab + kt * BK;
#pragma unroll
            for (int i = 0; i < 4; i++) {
                int idx = tid + i * NT;
                int r = idx >> 3, c = (idx & 7) << 2;
                cp16(s + r * SA + c, g + (size_t)r * lda + c);
            }
        }
        {
            float* s = Bs + buf * BN * SA;
            const float* g = Bb + kt * BK;
#pragma unroll
            for (int i = 0; i < 4; i++) {
                int idx = tid + i * NT;
                int r = idx >> 3, c = (idx & 7) << 2;
                cp16(s + r * SA + c, g + (size_t)r * ldb + c);
            }
        }
    };

    const int nkt = K / BK;
    load_stage(0, 0);
    cp_commit();

    for (int kt = 0; kt < nkt; kt++) {
        const int buf = kt & 1;
        if (kt + 1 < nkt) load_stage(buf ^ 1, kt + 1);
        cp_commit();
        cp_wait1();
        __syncthreads();

        const float* as = As + buf * BM * SA;
        const float* bs = Bs + buf * BN * SA;
#pragma unroll
        for (int kk = 0; kk < BK; kk += 8) {
            unsigned af[4][4], bf[4][2];
            const int ca = kk + (lane & 3);
#pragma unroll
            for (int mi = 0; mi < 4; mi++) {
                const float* p = as + (wm * 64 + mi * 16 + (lane >> 2)) * SA + ca;
                af[mi][0] = ldcvt<CVT>(p[0]);
                af[mi][1] = ldcvt<CVT>(p[8 * SA]);
                af[mi][2] = ldcvt<CVT>(p[4]);
                af[mi][3] = ldcvt<CVT>(p[8 * SA + 4]);
            }
#pragma unroll
            for (int ni = 0; ni < 4; ni++) {
                const float* p = bs + (wn * 32 + ni * 8 + (lane >> 2)) * SA + ca;
                bf[ni][0] = ldcvt<CVT>(p[0]);
                bf[ni][1] = ldcvt<CVT>(p[4]);
            }
#pragma unroll
            for (int mi = 0; mi < 4; mi++)
#pragma unroll
                for (int ni = 0; ni < 4; ni++) mma8(acc[mi][ni], af[mi], bf[ni]);
        }
        __syncthreads();
    }

    float* Cb = C + (size_t)bz * sC;
#pragma unroll
    for (int mi = 0; mi < 4; mi++) {
#pragma unroll
        for (int ni = 0; ni < 4; ni++) {
            const int row = by * BM + wm * 64 + mi * 16 + (lane >> 2);
            const int col = bx * BN + wn * 32 + ni * 8 + ((lane & 3) << 1);
            float v0 = acc[mi][ni][0] * alpha, v1 = acc[mi][ni][1] * alpha;
            float v2 = acc[mi][ni][2] * alpha, v3 = acc[mi][ni][3] * alpha;
            if (ROUND) {
                v0 = __uint_as_float(f2tf(v0));
                v1 = __uint_as_float(f2tf(v1));
                v2 = __uint_as_float(f2tf(v2));
                v3 = __uint_as_float(f2tf(v3));
            }
            *reinterpret_cast<float2*>(Cb + (size_t)row * ldc + col) = make_float2(v0, v1);
            *reinterpret_cast<float2*>(Cb + (size_t)(row + 8) * ldc + col) = make_float2(v2, v3);
        }
    }
}

// ---------------------------------------------------------------------------
// GEMM NN (P @ V):  C[m,n] = sum_k A[m,k] * B[k,n]
//   A: [T,T] row-major (P, lda=T), B: [T,D] row-major (V, ldb=D).
//   Causal: K extent per M-tile = (by+1)*BM (P zero-padded up to tile boundary).
// ---------------------------------------------------------------------------
template <bool CVT>
__global__ void __launch_bounds__(NT)
gemm_nn_kernel(const float* __restrict__ A, const float* __restrict__ B,
               float* __restrict__ C, int lda, int ldb, int ldc,
               long long sA, long long sB, long long sC) {
    const int bx = blockIdx.x, by = blockIdx.y, bz = blockIdx.z;

    extern __shared__ float smem[];
    float* As = smem;                 // [2][BM][SA]
    float* Bs = smem + 2 * BM * SA;   // [2][BK][SBNN]

    const float* Ab = A + (size_t)bz * sA + (size_t)by * BM * lda;
    const float* Bb = B + (size_t)bz * sB + bx * BN;

    const int tid = threadIdx.x, lane = tid & 31, wid = tid >> 5;
    const int wm = wid >> 2, wn = wid & 3;

    float acc[4][4][4];
#pragma unroll
    for (int i = 0; i < 4; i++)
#pragma unroll
        for (int j = 0; j < 4; j++)
#pragma unroll
            for (int k = 0; k < 4; k++) acc[i][j][k] = 0.f;

    auto load_stage = [&](int buf, int kt) {
        {
            float* s = As + buf * BM * SA;
            const float* g = Ab + kt * BK;
#pragma unroll
            for (int i = 0; i < 4; i++) {
                int idx = tid + i * NT;
                int r = idx >> 3, c = (idx & 7) << 2;
                cp16(s + r * SA + c, g + (size_t)r * lda + c);
            }
        }
        {
            float* s = Bs + buf * BK * SBNN;
            const float* g = Bb + (size_t)kt * BK * ldb;
#pragma unroll
            for (int i = 0; i < 4; i++) {
                int idx = tid + i * NT;
                int r = idx >> 5, c = (idx & 31) << 2;
                cp16(s + r * SBNN + c, g + (size_t)r * ldb + c);
            }
        }
    };

    const int nkt = (by + 1) * (BM / BK);   // causal K extent
    load_stage(0, 0);
    cp_commit();

    for (int kt = 0; kt < nkt; kt++) {
        const int buf = kt & 1;
        if (kt + 1 < nkt) load_stage(buf ^ 1, kt + 1);
        cp_commit();
        cp_wait1();
        __syncthreads();

        const float* as = As + buf * BM * SA;
        const float* bs = Bs + buf * BK * SBNN;
#pragma unroll
        for (int kk = 0; kk < BK; kk += 8) {
            unsigned af[4][4], bf[4][2];
            const int ca = kk + (lane & 3);
#pragma unroll
            for (int mi = 0; mi < 4; mi++) {
                const float* p = as + (wm * 64 + mi * 16 + (lane >> 2)) * SA + ca;
                af[mi][0] = ldcvt<CVT>(p[0]);
                af[mi][1] = ldcvt<CVT>(p[8 * SA]);
                af[mi][2] = ldcvt<CVT>(p[4]);
                af[mi][3] = ldcvt<CVT>(p[8 * SA + 4]);
            }
#pragma unroll
            for (int ni = 0; ni < 4; ni++) {
                const float* p = bs + (kk + (lane & 3)) * SBNN + wn * 32 + ni * 8 + (lane >> 2);
                bf[ni][0] = ldcvt<CVT>(p[0]);
                bf[ni][1] = ldcvt<CVT>(p[4 * SBNN]);
            }
#pragma unroll
            for (int mi = 0; mi < 4; mi++)
#pragma unroll
                for (int ni = 0; ni < 4; ni++) mma8(acc[mi][ni], af[mi], bf[ni]);
        }
        __syncthreads();
    }

    float* Cb = C + (size_t)bz * sC;
#pragma unroll
    for (int mi = 0; mi < 4; mi++) {
#pragma unroll
        for (int ni = 0; ni < 4; ni++) {
            const int row = by * BM + wm * 64 + mi * 16 + (lane >> 2);
            const int col = bx * BN + wn * 32 + ni * 8 + ((lane & 3) << 1);
            *reinterpret_cast<float2*>(Cb + (size_t)row * ldc + col) =
                make_float2(acc[mi][ni][0], acc[mi][ni][1]);
            *reinterpret_cast<float2*>(Cb + (size_t)(row + 8) * ldc + col) =
                make_float2(acc[mi][ni][2], acc[mi][ni][3]);
        }
    }
}

// ---------------------------------------------------------------------------
// Causal row softmax over S (in place). Row q reads j in [0, q]; writes
// tf32-rounded probabilities; zero-fills j in (q, roundup128(q+1)) so the
// P@V GEMM can read full 128-wide K tiles.
// ---------------------------------------------------------------------------
__global__ void __launch_bounds__(256)
softmax_causal_kernel(float* __restrict__ S) {
    const int q = blockIdx.x, b = blockIdx.y;
    float* row = S + ((size_t)b * T + q) * T;
    const int L = q + 1;
    const int Lpad = ((q >> 7) + 1) << 7;

    __shared__ float srow[T];
    __shared__ float red[8];
    __shared__ float bc;
    const int tid = threadIdx.x;

    float mx = -3.4e38f;
    for (int j = tid; j < L; j += 256) {
        float v = row[j];
        srow[j] = v;
        mx = fmaxf(mx, v);
    }
#pragma unroll
    for (int o = 16; o; o >>= 1) mx = fmaxf(mx, __shfl_xor_sync(0xffffffffu, mx, o));
    if ((tid & 31) == 0) red[tid >> 5] = mx;
    __syncthreads();
    if (tid == 0) {
        float m = red[0];
#pragma unroll
        for (int i = 1; i < 8; i++) m = fmaxf(m, red[i]);
        bc = m;
    }
    __syncthreads();
    mx = bc;

    float sum = 0.f;
    for (int j = tid; j < L; j += 256) {
        float e = __expf(srow[j] - mx);
        srow[j] = e;
        sum += e;
    }
#pragma unroll
    for (int o = 16; o; o >>= 1) sum += __shfl_xor_sync(0xffffffffu, sum, o);
    __syncthreads();
    if ((tid & 31) == 0) red[tid >> 5] = sum;
    __syncthreads();
    if (tid == 0) {
        float s = 0.f;
#pragma unroll
        for (int i = 0; i < 8; i++) s += red[i];
        bc = s;
    }
    __syncthreads();
    const float inv = 1.f / bc;

    for (int j = tid; j < L; j += 256)
        row[j] = __uint_as_float(f2tf(srow[j] * inv));
    for (int j = L + tid; j < Lpad; j += 256) row[j] = 0.f;
}

// ---------------------------------------------------------------------------
// launch
// ---------------------------------------------------------------------------
extern "C" void kernel_launch(void* const* d_in, const int* in_sizes, int n_in,
                              void* d_out, int out_size) {
    const float* X  = (const float*)d_in[0];
    const float* Wq = (const float*)d_in[1];
    const float* Wk = (const float*)d_in[2];
    const float* Wv = (const float*)d_in[3];
    float* out = (float*)d_out;

    float *Qp, *Kp, *Vp, *Sp;
    cudaGetSymbolAddress((void**)&Qp, g_Q);
    cudaGetSymbolAddress((void**)&Kp, g_K);
    cudaGetSymbolAddress((void**)&Vp, g_V);
    cudaGetSymbolAddress((void**)&Sp, g_S);

    cudaFuncSetAttribute(gemm_tn_kernel<true, false, true>,
                         cudaFuncAttributeMaxDynamicSharedMemorySize, SMEM_TN);
    cudaFuncSetAttribute(gemm_tn_kernel<false, true, false>,
                         cudaFuncAttributeMaxDynamicSharedMemorySize, SMEM_TN);
    cudaFuncSetAttribute(gemm_nn_kernel<false>,
                         cudaFuncAttributeMaxDynamicSharedMemorySize, SMEM_NN);

    const float inv_sqrt_d = 1.0f / 32.0f;   // 1/sqrt(1024)

    // QKV projections: [8192,1024] = X @ W^T  (Q pre-scaled by 1/sqrt(d))
    dim3 g1(D / BN, MQKV / BM, 1);
    gemm_tn_kernel<true, false, true><<<g1, NT, SMEM_TN>>>(
        X, Wq, Qp, D, D, D, D, 0, 0, 0, inv_sqrt_d);
    gemm_tn_kernel<true, false, true><<<g1, NT, SMEM_TN>>>(
        X, Wk, Kp, D, D, D, D, 0, 0, 0, 1.0f);
    gemm_tn_kernel<true, false, true><<<g1, NT, SMEM_TN>>>(
        X, Wv, Vp, D, D, D, D, 0, 0, 0, 1.0f);

    // S = Q K^T per batch, causal tiles only
    dim3 g2(T / BN, T / BM, BATCH);
    gemm_tn_kernel<false, true, false><<<g2, NT, SMEM_TN>>>(
        Qp, Kp, Sp, D, D, D, T,
        (long long)T * D, (long long)T * D, (long long)T * T, 1.0f);

    // P = softmax(S) in place (+ zero-pad diagonal block remainder)
    dim3 g3(T, BATCH);
    softmax_causal_kernel<<<g3, 256>>>(Sp);

    // out = P V per batch, causal K extent
    dim3 g4(D / BN, T / BM, BATCH);
    gemm_nn_kernel<false><<<g4, NT, SMEM_NN>>>(
        Sp, Vp, out, T, D, D,
        (long long)T * T, (long long)T * D, (long long)T * D);
}

// round 3
// speedup vs baseline: 1.4130x; 1.4130x over previous
#include <cuda_runtime.h>
#include <cstdint>

// ---------------------------------------------------------------------------
// SelfAttention B=4, T=2048, D=1024, causal — mma.sync tf32 + ldmatrix edition.
// (tcgen05 rejected by this toolchain: ptxas targets sm_100 without 'a'.)
//   round(X), round(W) -> tf32-exact operands
//   Q = Xr Wq^T / 32 ; K = Xr Wk^T ; Vt = (Xr Wv^T)^T   (one launch, bz=0/1/2)
//   S = Q K^T (causal tiles)  ->  P = softmax(S) (tf32-rounded, zero-padded)
//   out = P Vt^T              (causal K extent per M tile)
// GEMM: 128x128x32 tiles, 3-stage cp.async, XOR-swizzled smem, ldmatrix.x4
// operand fetch, m16n8k8 tf32 MMA, 8 warps (64x32 each), 2 CTAs/SM.
// ---------------------------------------------------------------------------

namespace {
constexpr int BATCH = 4;
constexpr int T     = 2048;
constexpr int D     = 1024;
constexpr int MQKV  = BATCH * T;          // 8192

constexpr int BM = 128, BN = 128, BK = 32;   // BK in floats (128 B rows)
constexpr int STG = 3;                        // pipeline stages
constexpr int NT  = 256;                      // 8 warps

constexpr int A_STG = BM * 128;               // 16384 B
constexpr int B_STG = BN * 128;               // 16384 B
constexpr int STG_BYTES = A_STG + B_STG;      // 32768 B
constexpr int SMEM_TOTAL = STG * STG_BYTES;   // 98304 B
}

// scratch (device globals — allocation-free)
__device__ float g_Xr[(size_t)MQKV * D];
__device__ float g_Wq[(size_t)D * D];
__device__ float g_Wk[(size_t)D * D];
__device__ float g_Wv[(size_t)D * D];
__device__ float g_Q [(size_t)MQKV * D];
__device__ float g_K [(size_t)MQKV * D];
__device__ float g_Vt[(size_t)D * MQKV];     // transposed V: [D][B*T]
__device__ float g_S [(size_t)BATCH * T * T];

// ---------------------------------------------------------------------------
// helpers
// ---------------------------------------------------------------------------
__device__ __forceinline__ unsigned f2tf(float x) {
    unsigned r; asm("cvt.rna.tf32.f32 %0, %1;" : "=r"(r) : "f"(x)); return r;
}
__device__ __forceinline__ float tf32r(float x) { return __uint_as_float(f2tf(x)); }

__device__ __forceinline__ uint32_t smem_u32(const void* p) {
    uint32_t a;
    asm("{ .reg .u64 t; cvta.to.shared.u64 t, %1; cvt.u32.u64 %0, t; }" : "=r"(a) : "l"(p));
    return a;
}

__device__ __forceinline__ void cp16s(uint32_t s, const void* g) {
    asm volatile("cp.async.cg.shared.global [%0], [%1], 16;" ::"r"(s), "l"(g));
}
__device__ __forceinline__ void cp_commit() { asm volatile("cp.async.commit_group;"); }
__device__ __forceinline__ void cp_wait1()  { asm volatile("cp.async.wait_group 1;"); }

__device__ __forceinline__ void ldsm4(uint32_t& r0, uint32_t& r1, uint32_t& r2,
                                      uint32_t& r3, uint32_t addr) {
    asm volatile("ldmatrix.sync.aligned.m8n8.x4.shared.b16 {%0,%1,%2,%3}, [%4];"
                 : "=r"(r0), "=r"(r1), "=r"(r2), "=r"(r3) : "r"(addr));
}

__device__ __forceinline__ void mma8(float* c, const uint32_t* a, const uint32_t* b) {
    asm volatile(
        "mma.sync.aligned.m16n8k8.row.col.f32.tf32.tf32.f32 "
        "{%0,%1,%2,%3}, {%4,%5,%6,%7}, {%8,%9}, {%0,%1,%2,%3};"
        : "+f"(c[0]), "+f"(c[1]), "+f"(c[2]), "+f"(c[3])
        : "r"(a[0]), "r"(a[1]), "r"(a[2]), "r"(a[3]), "r"(b[0]), "r"(b[1]));
}

// ---------------------------------------------------------------------------
// TN GEMM:  C[m,n] = sum_k A[m,k] * B[n,k]   (both K-major)
//   MODE 0: S = QK^T (causal tile skip)
//   MODE 1: out = P Vt^T (causal K extent)
//   MODE 2: QKV projection (bz selects W/C; bz==2 writes V transposed)
// ---------------------------------------------------------------------------
template <int MODE>
__global__ void __launch_bounds__(NT, 2)
tc_gemm(const float* __restrict__ A,
        const float* __restrict__ B0, const float* __restrict__ B1,
        const float* __restrict__ B2,
        float* __restrict__ C0, float* __restrict__ C1, float* __restrict__ C2,
        int K, int lda, int ldb, int ldc,
        long long sA, long long sB, long long sC) {
    const int bx = blockIdx.x, by = blockIdx.y, bz = blockIdx.z;
    if (MODE == 0 && bx > by) return;            // causal tile skip
    if (MODE == 1) K = (by + 1) * BM;            // causal K extent

    extern __shared__ char smem[];
    const uint32_t sb = smem_u32(smem);
    const int tid = threadIdx.x, w = tid >> 5, lane = tid & 31;
    const int wm = w >> 2, wn = w & 3;           // 2 x 4 warps, 64x32 each

    const float* Bsel = (MODE == 2) ? (bz == 0 ? B0 : bz == 1 ? B1 : B2) : B0;
    const float* Ab = A + (size_t)bz * sA + (size_t)by * BM * lda;
    const float* Bb = Bsel + (size_t)bz * sB + (size_t)bx * BN * ldb;

    // cp.async per-thread pattern: idx = tid + i*NT; row = idx>>3, 16B seg = idx&7
    const int cr = tid >> 3, cc = tid & 7;       // row 0..31 (+32*i), seg 0..7
    const uint32_t c_sw = (uint32_t)(cc * 16) ^ ((uint32_t)(cr & 7) << 4);

    // ldmatrix per-lane geometry
    const int l7 = lane & 7, lb3 = (lane >> 3) & 1, lb4 = (lane >> 4) & 1;
    const uint32_t xr = (uint32_t)l7 << 4;
    const uint32_t aRow0 = (uint32_t)(wm * 64 + lb3 * 8 + l7) * 128;   // + mi*2048
    const uint32_t aSeg  = (uint32_t)lb4 * 16;
    const uint32_t bRow0 = (uint32_t)(wn * 32 + lb4 * 8 + l7) * 128;   // + nj*2048
    const uint32_t bSeg  = (uint32_t)lb3 * 16;

    float acc[4][4][4];
#pragma unroll
    for (int i = 0; i < 4; i++)
#pragma unroll
        for (int j = 0; j < 4; j++)
#pragma unroll
            for (int k = 0; k < 4; k++) acc[i][j][k] = 0.f;

    auto ldst = [&](int slot, int kt) {
        const uint32_t stg = sb + slot * STG_BYTES;
        const float* ag = Ab + kt * BK;
#pragma unroll
        for (int i = 0; i < 4; i++) {
            int r = cr + i * 32;
            cp16s(stg + (uint32_t)r * 128 + c_sw, ag + (size_t)r * lda + cc * 4);
        }
        const float* bg = Bb + kt * BK;
#pragma unroll
        for (int i = 0; i < 4; i++) {
            int r = cr + i * 32;
            cp16s(stg + A_STG + (uint32_t)r * 128 + c_sw, bg + (size_t)r * ldb + cc * 4);
        }
    };

    const int nkt = K / BK;
    ldst(0, 0); cp_commit();
    if (nkt > 1) ldst(1, 1);
    cp_commit();

    int slot = 0;
    for (int kt = 0; kt < nkt; kt++) {
        cp_wait1();
        __syncthreads();
        if (kt + 2 < nkt) {
            int ns = slot + 2; if (ns >= STG) ns -= STG;
            ldst(ns, kt + 2);
        }
        cp_commit();

        const uint32_t astg = sb + slot * STG_BYTES;
        const uint32_t bstg = astg + A_STG;
#pragma unroll
        for (int kk4 = 0; kk4 < 128; kk4 += 32) {
            uint32_t af[4][4], bf[4][2];
            const uint32_t aoff = ((uint32_t)kk4 | aSeg) ^ xr;
            const uint32_t boff = ((uint32_t)kk4 | bSeg) ^ xr;
#pragma unroll
            for (int mi = 0; mi < 4; mi++)
                ldsm4(af[mi][0], af[mi][1], af[mi][2], af[mi][3],
                      astg + aRow0 + (uint32_t)mi * 2048 + aoff);
#pragma unroll
            for (int nj = 0; nj < 2; nj++) {
                uint32_t r0, r1, r2, r3;
                ldsm4(r0, r1, r2, r3, bstg + bRow0 + (uint32_t)nj * 2048 + boff);
                bf[nj * 2][0] = r0; bf[nj * 2][1] = r1;
                bf[nj * 2 + 1][0] = r2; bf[nj * 2 + 1][1] = r3;
            }
#pragma unroll
            for (int mi = 0; mi < 4; mi++)
#pragma unroll
                for (int ni = 0; ni < 4; ni++) mma8(acc[mi][ni], af[mi], bf[ni]);
        }
        __syncthreads();
        if (++slot == STG) slot = 0;
    }

    // ---- epilogue ----
#pragma unroll
    for (int mi = 0; mi < 4; mi++) {
#pragma unroll
        for (int ni = 0; ni < 4; ni++) {
            const int row = by * BM + wm * 64 + mi * 16 + (lane >> 2);
            const int col = bx * BN + wn * 32 + ni * 8 + ((lane & 3) << 1);
            float v0 = acc[mi][ni][0], v1 = acc[mi][ni][1];
            float v2 = acc[mi][ni][2], v3 = acc[mi][ni][3];
            if (MODE == 2) {
                if (bz == 0) { v0 *= 0.03125f; v1 *= 0.03125f; v2 *= 0.03125f; v3 *= 0.03125f; }
                v0 = tf32r(v0); v1 = tf32r(v1); v2 = tf32r(v2); v3 = tf32r(v3);
                if (bz == 2) {   // Vt: [D][MQKV], transposed store
                    C2[(size_t)col * MQKV + row]           = v0;
                    C2[(size_t)(col + 1) * MQKV + row]     = v1;
                    C2[(size_t)col * MQKV + row + 8]       = v2;
                    C2[(size_t)(col + 1) * MQKV + row + 8] = v3;
                } else {
                    float* Cd = (bz == 0) ? C0 : C1;
                    *reinterpret_cast<float2*>(Cd + (size_t)row * ldc + col) = make_float2(v0, v1);
                    *reinterpret_cast<float2*>(Cd + (size_t)(row + 8) * ldc + col) = make_float2(v2, v3);
                }
            } else {
                float* Cd = C0 + (size_t)bz * sC;
                *reinterpret_cast<float2*>(Cd + (size_t)row * ldc + col) = make_float2(v0, v1);
                *reinterpret_cast<float2*>(Cd + (size_t)(row + 8) * ldc + col) = make_float2(v2, v3);
            }
        }
    }
}

// ---------------------------------------------------------------------------
// elementwise tf32 rounding (float4)
// ---------------------------------------------------------------------------
__global__ void __launch_bounds__(256)
round_tf32_kernel(const float* __restrict__ in, float* __restrict__ out, int n4) {
    int i = blockIdx.x * 256 + threadIdx.x;
    if (i >= n4) return;
    float4 v = reinterpret_cast<const float4*>(in)[i];
    v.x = tf32r(v.x); v.y = tf32r(v.y); v.z = tf32r(v.z); v.w = tf32r(v.w);
    reinterpret_cast<float4*>(out)[i] = v;
}

// ---------------------------------------------------------------------------
// causal row softmax (in place) + tf32 round + zero-pad to 128 boundary
// ---------------------------------------------------------------------------
__global__ void __launch_bounds__(256)
softmax_causal_kernel(float* __restrict__ S) {
    const int q = blockIdx.x, b = blockIdx.y;
    float* row = S + ((size_t)b * T + q) * T;
    const int L = q + 1;
    const int Lpad = ((q >> 7) + 1) << 7;

    __shared__ float srow[T];
    __shared__ float red[8];
    __shared__ float bc;
    const int tid = threadIdx.x;

    float mx = -3.4e38f;
    for (int j = tid; j < L; j += 256) {
        float v = row[j];
        srow[j] = v;
        mx = fmaxf(mx, v);
    }
#pragma unroll
    for (int o = 16; o; o >>= 1) mx = fmaxf(mx, __shfl_xor_sync(0xffffffffu, mx, o));
    if ((tid & 31) == 0) red[tid >> 5] = mx;
    __syncthreads();
    if (tid == 0) {
        float m = red[0];
#pragma unroll
        for (int i = 1; i < 8; i++) m = fmaxf(m, red[i]);
        bc = m;
    }
    __syncthreads();
    mx = bc;

    float sum = 0.f;
    for (int j = tid; j < L; j += 256) {
        float e = __expf(srow[j] - mx);
        srow[j] = e;
        sum += e;
    }
#pragma unroll
    for (int o = 16; o; o >>= 1) sum += __shfl_xor_sync(0xffffffffu, sum, o);
    __syncthreads();
    if ((tid & 31) == 0) red[tid >> 5] = sum;
    __syncthreads();
    if (tid == 0) {
        float s = 0.f;
#pragma unroll
        for (int i = 0; i < 8; i++) s += red[i];
        bc = s;
    }
    __syncthreads();
    const float inv = 1.f / bc;

    for (int j = tid; j < L; j += 256) row[j] = tf32r(srow[j] * inv);
    for (int j = L + tid; j < Lpad; j += 256) row[j] = 0.f;
}

// ---------------------------------------------------------------------------
// launch
// ---------------------------------------------------------------------------
extern "C" void kernel_launch(void* const* d_in, const int* in_sizes, int n_in,
                              void* d_out, int out_size) {
    const float* X  = (const float*)d_in[0];
    const float* Wq = (const float*)d_in[1];
    const float* Wk = (const float*)d_in[2];
    const float* Wv = (const float*)d_in[3];
    float* out = (float*)d_out;

    float *Xr, *Wqr, *Wkr, *Wvr, *Qp, *Kp, *Vtp, *Sp;
    cudaGetSymbolAddress((void**)&Xr, g_Xr);
    cudaGetSymbolAddress((void**)&Wqr, g_Wq);
    cudaGetSymbolAddress((void**)&Wkr, g_Wk);
    cudaGetSymbolAddress((void**)&Wvr, g_Wv);
    cudaGetSymbolAddress((void**)&Qp, g_Q);
    cudaGetSymbolAddress((void**)&Kp, g_K);
    cudaGetSymbolAddress((void**)&Vtp, g_Vt);
    cudaGetSymbolAddress((void**)&Sp, g_S);

    cudaFuncSetAttribute(tc_gemm<0>, cudaFuncAttributeMaxDynamicSharedMemorySize, SMEM_TOTAL);
    cudaFuncSetAttribute(tc_gemm<1>, cudaFuncAttributeMaxDynamicSharedMemorySize, SMEM_TOTAL);
    cudaFuncSetAttribute(tc_gemm<2>, cudaFuncAttributeMaxDynamicSharedMemorySize, SMEM_TOTAL);

    // tf32-exact operands
    const int nX4 = MQKV * D / 4, nW4 = D * D / 4;
    round_tf32_kernel<<<(nX4 + 255) / 256, 256>>>(X, Xr, nX4);
    round_tf32_kernel<<<(nW4 + 255) / 256, 256>>>(Wq, Wqr, nW4);
    round_tf32_kernel<<<(nW4 + 255) / 256, 256>>>(Wk, Wkr, nW4);
    round_tf32_kernel<<<(nW4 + 255) / 256, 256>>>(Wv, Wvr, nW4);

    // QKV projections in one launch (bz = 0:Q, 1:K, 2:Vt)
    dim3 gp(D / BN, MQKV / BM, 3);
    tc_gemm<2><<<gp, NT, SMEM_TOTAL>>>(
        Xr, Wqr, Wkr, Wvr, Qp, Kp, Vtp,
        D, D, D, D, 0, 0, 0);

    // S = Q K^T (causal tiles only)
    dim3 gs(T / BN, T / BM, BATCH);
    tc_gemm<0><<<gs, NT, SMEM_TOTAL>>>(
        Qp, Kp, nullptr, nullptr, Sp, nullptr, nullptr,
        D, D, D, T,
        (long long)T * D, (long long)T * D, (long long)T * T);

    // P = softmax(S)
    dim3 gsm(T, BATCH);
    softmax_causal_kernel<<<gsm, 256>>>(Sp);

    // out = P V   (B = Vt: rows d, batch column offset bz*T)
    dim3 gv(D / BN, T / BM, BATCH);
    tc_gemm<1><<<gv, NT, SMEM_TOTAL>>>(
        Sp, Vtp, nullptr, nullptr, out, nullptr, nullptr,
        T, T, MQKV, D,
        (long long)T * T, (long long)T, (long long)T * D);
}